// round 6
// baseline (speedup 1.0000x reference)
#include <cuda_runtime.h>
#include <cstdint>

#define B_    8
#define CIN_  128
#define H_    28
#define W_    28
#define COUT_ 256
#define NCB_  64
#define KC_   16
#define SUB_  18
#define NPIX_ 784
#define NTOT_ (B_ * NPIX_)   // 6272

// scratch (allocation-free rule: __device__ globals); 16B-aligned for uint4 access
__device__ __align__(16) int8_t  g_idx[NTOT_ * NCB_];           // idx[n][c], 401 KB
__device__ __align__(16) int16_t g_lut16[NCB_ * KC_ * COUT_];   // 512 KB
__device__ int    g_y2r[NCB_ * KC_];            // 4 KB

// ---------------------------------------------------------------------------
// Kernel P: lut int32 -> int16 repack + y2r = round(y2/den) per (codebook, k)
// Mimics XLA fp32: elementwise dequant (one rounded mul), sequential FMA
// accumulation, fp32 div, round-half-even.
// ---------------------------------------------------------------------------
__global__ void __launch_bounds__(256) prep_kernel(
    const int* __restrict__ lut_q, const int* __restrict__ cq,
    const float* __restrict__ cs, const int* __restrict__ cz,
    const float* __restrict__ xs)
{
    int i = blockIdx.x * 256 + threadIdx.x;
    for (int t = i; t < NCB_ * KC_ * COUT_; t += gridDim.x * 256)
        g_lut16[t] = (int16_t)lut_q[t];
    if (i < NCB_ * KC_) {
        int c = i >> 4;
        float s = cs[c];
        float z = (float)cz[c];
        const int* q = cq + i * SUB_;
        float acc = 0.f;
        #pragma unroll
        for (int u = 0; u < SUB_; ++u) {
            float cv = __fmul_rn((float)q[u] - z, s);   // (q - z) exact, one rounding
            acc = __fmaf_rn(cv, cv, acc);               // sequential fma sum
        }
        float den = __fmul_rn(xs[0], s);
        g_y2r[i] = __float2int_rn(__fdiv_rn(acc, den)); // round-half-even
    }
}

// ---------------------------------------------------------------------------
// Kernel A: per (codebook, batch) block — integer-exact distances + argmin.
// Codebook c touches input channels 2c, 2c+1 only (SUB = 2*9).
// dist_k = y2r[k] - 2 * sum_s (x_q - x_z)(c_q - c_z)   (int32 exact; the
// reference's round(xy/den) equals this integer since its fp noise << 0.5).
// First-min tie-break matches jnp.argmin.
// ---------------------------------------------------------------------------
__global__ void __launch_bounds__(256) idx_kernel(
    const int* __restrict__ xq, const int* __restrict__ xz_p,
    const int* __restrict__ cq, const int* __restrict__ cz_p)
{
    int c = blockIdx.x;   // codebook
    int b = blockIdx.y;   // batch
    __shared__ int sx[2][30][32];   // halo window, (x_q - x_z), pad=0
    __shared__ int sc[KC_][SUB_];   // (c_q - c_z)
    __shared__ int sy[KC_];
    int tid = threadIdx.x;
    int xz = xz_p[0];
    int cz = cz_p[c];

    for (int t = tid; t < 1800; t += 256) {
        int cc  = t / 900;
        int r   = (t % 900) / 30;
        int col = t % 30;
        int ih = r - 1, iw = col - 1;
        int v = 0;
        if ((unsigned)ih < 28u && (unsigned)iw < 28u)
            v = xq[(((b * CIN_) + 2 * c + cc) * H_ + ih) * W_ + iw] - xz;
        sx[cc][r][col] = v;
    }
    for (int t = tid; t < KC_ * SUB_; t += 256)
        sc[t / SUB_][t % SUB_] = cq[c * KC_ * SUB_ + t] - cz;
    if (tid < KC_) sy[tid] = g_y2r[c * KC_ + tid];
    __syncthreads();

    if (tid >= 196) return;           // 196 threads * 4 pixels = 784
    int p0  = tid * 4;                // 4|28 -> never crosses a row
    int oh  = tid / 7;
    int ow0 = (tid % 7) * 4;

    int w[2][3][6];                   // shared window of 4 adjacent pixels
    #pragma unroll
    for (int cc = 0; cc < 2; ++cc)
        #pragma unroll
        for (int i = 0; i < 3; ++i)
            #pragma unroll
            for (int col = 0; col < 6; ++col)
                w[cc][i][col] = sx[cc][oh + i][ow0 + col];

    int best0 = 0x7fffffff, best1 = 0x7fffffff, best2 = 0x7fffffff, best3 = 0x7fffffff;
    int bi0 = 0, bi1 = 0, bi2 = 0, bi3 = 0;
    for (int k = 0; k < KC_; ++k) {
        int d0 = 0, d1 = 0, d2 = 0, d3 = 0;
        #pragma unroll
        for (int s = 0; s < SUB_; ++s) {
            int cv = sc[k][s];                    // broadcast LDS
            int cc = s / 9, rr = (s % 9) / 3, jj = s % 3;
            d0 += w[cc][rr][jj + 0] * cv;
            d1 += w[cc][rr][jj + 1] * cv;
            d2 += w[cc][rr][jj + 2] * cv;
            d3 += w[cc][rr][jj + 3] * cv;
        }
        int y = sy[k];
        int t0 = y - 2 * d0; if (t0 < best0) { best0 = t0; bi0 = k; }
        int t1 = y - 2 * d1; if (t1 < best1) { best1 = t1; bi1 = k; }
        int t2 = y - 2 * d2; if (t2 < best2) { best2 = t2; bi2 = k; }
        int t3 = y - 2 * d3; if (t3 < best3) { best3 = t3; bi3 = k; }
    }
    int8_t* dst = g_idx + ((size_t)(b * NPIX_ + p0)) * NCB_ + c;
    dst[0]       = (int8_t)bi0;
    dst[NCB_]    = (int8_t)bi1;
    dst[2*NCB_]  = (int8_t)bi2;
    dst[3*NCB_]  = (int8_t)bi3;
}

// ---------------------------------------------------------------------------
// Kernel B: gather-accumulate 64 LUT rows per pixel.
// LUT pre-widened to int16 (no sign-extension byte tricks); staged in smem
// 4 codebooks (32 KB) at a time; inner op = LDS.64 (4 couts) + 2x VADD2.
// Block = 56 pixels. 256 threads = 64 cout-quads x 4 pixel-groups of 14.
// Epilogue: quantize to float32, transpose via smem float4 tile in two
// 28-pixel chunks, coalesced STG.128.
// ---------------------------------------------------------------------------
__global__ void __launch_bounds__(256) out_kernel(
    const int* __restrict__ bias_q,
    const float* __restrict__ lut_s, const int* __restrict__ lut_z,
    const float* __restrict__ bias_s, const int* __restrict__ bias_z,
    const float* __restrict__ out_s, const int* __restrict__ out_z,
    float* __restrict__ out)
{
    int tile = blockIdx.x;   // 0..13
    int b    = blockIdx.y;   // 0..7
    __shared__ __align__(16) int16_t s_lut16[4 * KC_ * COUT_];  // 32 KB (reused as out tile)
    __shared__ __align__(16) int8_t  s_idx[56 * NCB_];          // 3.5 KB
    int tid = threadIdx.x;
    int n0  = b * NPIX_ + tile * 56;

    {   // idx tile -> smem (16B vectors, aligned: n0*64 is 16B-multiple)
        const uint4* src = (const uint4*)(g_idx + (size_t)n0 * NCB_);
        uint4* dst = (uint4*)s_idx;
        if (tid < 224) dst[tid] = src[tid];
    }

    int co4 = tid & 63;   // cout quad: couts 4*co4 .. 4*co4+3
    int ng  = tid >> 6;   // pixel group: pixels ng*14 .. ng*14+13
    uint32_t accA[14], accB[14];   // int16x2 packed sums (|S|<=8128, no overflow)
    #pragma unroll
    for (int n = 0; n < 14; ++n) { accA[n] = 0u; accB[n] = 0u; }

    for (int g = 0; g < 16; ++g) {   // 4 codebooks per stage
        __syncthreads();
        const uint4* src = (const uint4*)(g_lut16 + g * 4 * KC_ * COUT_);
        uint4* dst = (uint4*)s_lut16;
        #pragma unroll
        for (int t = 0; t < 8; ++t) dst[tid + t * 256] = src[tid + t * 256];
        __syncthreads();
        #pragma unroll
        for (int nl = 0; nl < 14; ++nl) {
            int nn = ng * 14 + nl;
            uint32_t i0 = *(const uint32_t*)(s_idx + nn * 64 + g * 4);
            #pragma unroll
            for (int c4 = 0; c4 < 4; ++c4) {
                int kk = (int)((i0 >> (8 * c4)) & 0xFFu);
                const uint2* row = (const uint2*)(s_lut16 + (c4 * KC_ + kk) * COUT_) + co4;
                uint2 v = *row;                       // 4 couts as s16x2 pairs
                accA[nl] = __vadd2(accA[nl], v.x);    // couts 4co4+0, +1
                accB[nl] = __vadd2(accB[nl], v.y);    // couts 4co4+2, +3
            }
        }
    }

    float ls = lut_s[0];  int lz = lut_z[0];
    float bs = bias_s[0]; int bz = bias_z[0];
    float os = out_s[0];  float ozf = (float)out_z[0];
    float bd[4];
    #pragma unroll
    for (int j = 0; j < 4; ++j)
        bd[j] = __fmul_rn((float)(bias_q[co4 * 4 + j] - bz), bs);

    // Quantize all 14 pixels into float values (reference int8 cast to f32)
    float fq[14][4];
    #pragma unroll
    for (int nl = 0; nl < 14; ++nl) {
        int S[4];
        S[0] = (int)(short)(accA[nl] & 0xFFFFu);
        S[1] = ((int)accA[nl]) >> 16;
        S[2] = (int)(short)(accB[nl] & 0xFFFFu);
        S[3] = ((int)accB[nl]) >> 16;
        #pragma unroll
        for (int j = 0; j < 4; ++j) {
            float sum = __fmul_rn(ls, (float)(S[j] - 64 * lz));
            float o   = sum + bd[j];
            o = fmaxf(o, 0.f);                                  // relu
            float t = __fadd_rn(__fdiv_rn(o, os), ozf);         // true fp32 div
            t = fminf(t, 127.f);
            t = fmaxf(t, -128.f);
            fq[nl][j] = (float)__float2int_rn(t);               // half-even, matches jnp.round
        }
    }

    // Transpose + store in two 28-pixel chunks via float4 smem tile.
    // Layout: s4[nnL][co4] (float4) == scalar s_f[nnL*256 + co]
    float4* s4  = (float4*)s_lut16;              // 28*64*16 = 28672 B <= 32 KB
    float*  s_f = (float*)s_lut16;
    #pragma unroll
    for (int ch = 0; ch < 2; ++ch) {
        __syncthreads();
        if ((ng >> 1) == ch) {
            #pragma unroll
            for (int nl = 0; nl < 14; ++nl) {
                int nnL = (ng & 1) * 14 + nl;    // 0..27 within chunk
                s4[nnL * 64 + co4] = make_float4(fq[nl][0], fq[nl][1], fq[nl][2], fq[nl][3]);
            }
        }
        __syncthreads();
        // thread 'co' = tid gathers 28 pixels of its cout row, stores coalesced
        int co = tid;
        float v[28];
        #pragma unroll
        for (int p = 0; p < 28; ++p) v[p] = s_f[p * 256 + co];  // bank = co%32, conflict-free
        float4* dst = (float4*)(out + (size_t)b * COUT_ * NPIX_ + co * NPIX_ + tile * 56 + ch * 28);
        #pragma unroll
        for (int p = 0; p < 7; ++p)
            dst[p] = make_float4(v[4*p], v[4*p+1], v[4*p+2], v[4*p+3]);
    }
}

// ---------------------------------------------------------------------------
extern "C" void kernel_launch(void* const* d_in, const int* in_sizes, int n_in,
                              void* d_out, int out_size)
{
    // Insertion order confirmed on hardware (in_sizes[0]==802816);
    // alphabetical fallback kept for robustness.
    bool alpha = (in_sizes[0] == COUT_);   // bias_q first => alphabetical

    const int*   x_q    = (const int*)  d_in[alpha ? 11 : 0];
    const float* x_s    = (const float*)d_in[alpha ? 12 : 1];
    const int*   x_z    = (const int*)  d_in[alpha ? 13 : 2];
    const int*   cq     = (const int*)  d_in[3];
    const float* cs     = (const float*)d_in[4];
    const int*   cz     = (const int*)  d_in[5];
    const int*   lut_q  = (const int*)  d_in[6];
    const float* lut_s  = (const float*)d_in[7];
    const int*   lut_z  = (const int*)  d_in[8];
    const int*   bias_q = (const int*)  d_in[alpha ? 0 : 9];
    const float* bias_s = (const float*)d_in[alpha ? 1 : 10];
    const int*   bias_z = (const int*)  d_in[alpha ? 2 : 11];
    const float* out_s  = (const float*)d_in[alpha ? 9 : 12];
    const int*   out_z  = (const int*)  d_in[alpha ? 10 : 13];

    prep_kernel<<<64, 256>>>(lut_q, cq, cs, cz, x_s);
    idx_kernel<<<dim3(NCB_, B_), 256>>>(x_q, x_z, cq, cz);
    out_kernel<<<dim3(14, B_), 256>>>(bias_q, lut_s, lut_z, bias_s, bias_z,
                                      out_s, out_z, (float*)d_out);
}

// round 9
// speedup vs baseline: 1.2965x; 1.2965x over previous
#include <cuda_runtime.h>
#include <cstdint>

#define B_    8
#define CIN_  128
#define H_    28
#define W_    28
#define COUT_ 256
#define NCB_  64
#define KC_   16
#define SUB_  18
#define NPIX_ 784
#define NTOT_ (B_ * NPIX_)   // 6272

// scratch (allocation-free rule: __device__ globals); 16B-aligned for uint4 access
__device__ __align__(16) int8_t  g_idx[NTOT_ * NCB_];           // idx[n][c], 401 KB
__device__ __align__(16) int16_t g_lut16[NCB_ * KC_ * COUT_];   // 512 KB
__device__ int    g_y2r[NCB_ * KC_];            // 4 KB

// ---------------------------------------------------------------------------
// Kernel P: lut int32 -> int16 repack (vectorized LDG.128 -> STG.64;
// 256 blocks x 256 thr x 4 elems = full 262144 coverage) +
// y2r = round(y2/den) per (codebook, k) — BIT-IDENTICAL math to the passing
// round-6 version (elementwise dequant, sequential FMA, div, rn).
// ---------------------------------------------------------------------------
__global__ void __launch_bounds__(256) prep_kernel(
    const int* __restrict__ lut_q, const int* __restrict__ cq,
    const float* __restrict__ cs, const int* __restrict__ cz,
    const float* __restrict__ xs)
{
    int i = blockIdx.x * 256 + threadIdx.x;   // 65536 threads
    {   // repack 4 int32 -> 4 int16 per thread
        const int4* src = (const int4*)lut_q;
        int4 v = src[i];
        uint32_t lo = ((uint32_t)v.x & 0xFFFFu) | ((uint32_t)v.y << 16);
        uint32_t hi = ((uint32_t)v.z & 0xFFFFu) | ((uint32_t)v.w << 16);
        ((uint2*)g_lut16)[i] = make_uint2(lo, hi);
    }
    if (i < NCB_ * KC_) {
        int c = i >> 4;
        float s = cs[c];
        float z = (float)cz[c];
        const int* q = cq + i * SUB_;
        float acc = 0.f;
        #pragma unroll
        for (int u = 0; u < SUB_; ++u) {
            float cv = __fmul_rn((float)q[u] - z, s);   // (q - z) exact, one rounding
            acc = __fmaf_rn(cv, cv, acc);               // sequential fma sum
        }
        float den = __fmul_rn(xs[0], s);
        g_y2r[i] = __float2int_rn(__fdiv_rn(acc, den)); // round-half-even
    }
}

// ---------------------------------------------------------------------------
// Kernel A: per (codebook, batch) block — integer-exact distances + argmin.
// (unchanged from passing round-6 kernel)
// ---------------------------------------------------------------------------
__global__ void __launch_bounds__(256) idx_kernel(
    const int* __restrict__ xq, const int* __restrict__ xz_p,
    const int* __restrict__ cq, const int* __restrict__ cz_p)
{
    int c = blockIdx.x;   // codebook
    int b = blockIdx.y;   // batch
    __shared__ int sx[2][30][32];   // halo window, (x_q - x_z), pad=0
    __shared__ int sc[KC_][SUB_];   // (c_q - c_z)
    __shared__ int sy[KC_];
    int tid = threadIdx.x;
    int xz = xz_p[0];
    int cz = cz_p[c];

    for (int t = tid; t < 1800; t += 256) {
        int cc  = t / 900;
        int r   = (t % 900) / 30;
        int col = t % 30;
        int ih = r - 1, iw = col - 1;
        int v = 0;
        if ((unsigned)ih < 28u && (unsigned)iw < 28u)
            v = xq[(((b * CIN_) + 2 * c + cc) * H_ + ih) * W_ + iw] - xz;
        sx[cc][r][col] = v;
    }
    for (int t = tid; t < KC_ * SUB_; t += 256)
        sc[t / SUB_][t % SUB_] = cq[c * KC_ * SUB_ + t] - cz;
    if (tid < KC_) sy[tid] = g_y2r[c * KC_ + tid];
    __syncthreads();

    if (tid >= 196) return;           // 196 threads * 4 pixels = 784
    int p0  = tid * 4;                // 4|28 -> never crosses a row
    int oh  = tid / 7;
    int ow0 = (tid % 7) * 4;

    int w[2][3][6];                   // shared window of 4 adjacent pixels
    #pragma unroll
    for (int cc = 0; cc < 2; ++cc)
        #pragma unroll
        for (int i = 0; i < 3; ++i)
            #pragma unroll
            for (int col = 0; col < 6; ++col)
                w[cc][i][col] = sx[cc][oh + i][ow0 + col];

    int best0 = 0x7fffffff, best1 = 0x7fffffff, best2 = 0x7fffffff, best3 = 0x7fffffff;
    int bi0 = 0, bi1 = 0, bi2 = 0, bi3 = 0;
    for (int k = 0; k < KC_; ++k) {
        int d0 = 0, d1 = 0, d2 = 0, d3 = 0;
        #pragma unroll
        for (int s = 0; s < SUB_; ++s) {
            int cv = sc[k][s];                    // broadcast LDS
            int cc = s / 9, rr = (s % 9) / 3, jj = s % 3;
            d0 += w[cc][rr][jj + 0] * cv;
            d1 += w[cc][rr][jj + 1] * cv;
            d2 += w[cc][rr][jj + 2] * cv;
            d3 += w[cc][rr][jj + 3] * cv;
        }
        int y = sy[k];
        int t0 = y - 2 * d0; if (t0 < best0) { best0 = t0; bi0 = k; }
        int t1 = y - 2 * d1; if (t1 < best1) { best1 = t1; bi1 = k; }
        int t2 = y - 2 * d2; if (t2 < best2) { best2 = t2; bi2 = k; }
        int t3 = y - 2 * d3; if (t3 < best3) { best3 = t3; bi3 = k; }
    }
    int8_t* dst = g_idx + ((size_t)(b * NPIX_ + p0)) * NCB_ + c;
    dst[0]       = (int8_t)bi0;
    dst[NCB_]    = (int8_t)bi1;
    dst[2*NCB_]  = (int8_t)bi2;
    dst[3*NCB_]  = (int8_t)bi3;
}

// ---------------------------------------------------------------------------
// Kernel B: gather-accumulate 64 LUT rows per pixel (int16x2 packed adds).
// Grid (14 tiles, 8 batch, 2 cout-halves) = 224 blocks (2/SM).
// Block = 56 pixels x 128 couts. 256 threads = 32 cout-quads x 8 groups of 7.
// LUT half staged 8 codebooks (32 KB) at a time, 8 stages, with register
// prefetch double-buffering (next stage LDGs issued before current gather).
// Warp layout: lane = co4 -> every gather LDS.64 is a coalesced 256B row;
// idx loads are warp-broadcast.
// Epilogue: quantize to float32, transpose via smem (reuse stage buffer),
// 128 threads each store one cout row (14 x STG.128).
// ---------------------------------------------------------------------------
__global__ void __launch_bounds__(256) out_kernel(
    const int* __restrict__ bias_q,
    const float* __restrict__ lut_s, const int* __restrict__ lut_z,
    const float* __restrict__ bias_s, const int* __restrict__ bias_z,
    const float* __restrict__ out_s, const int* __restrict__ out_z,
    float* __restrict__ out)
{
    int tile = blockIdx.x;   // 0..13
    int b    = blockIdx.y;   // 0..7
    int gz   = blockIdx.z;   // 0..1 (cout half)
    __shared__ __align__(16) int16_t s_lut16[8 * KC_ * 128];   // 32 KB stage (reused as out tile)
    __shared__ __align__(16) int8_t  s_idx[56 * NCB_];         // 3.5 KB
    int tid = threadIdx.x;
    int n0  = b * NPIX_ + tile * 56;

    {   // idx tile -> smem (16B vectors)
        const uint4* src = (const uint4*)(g_idx + (size_t)n0 * NCB_);
        uint4* dst = (uint4*)s_idx;
        if (tid < 224) dst[tid] = src[tid];
    }

    int co4 = tid & 31;   // cout quad within half: couts gz*128 + co4*4 ..+3
    int ng  = tid >> 5;   // pixel group: pixels ng*7 .. ng*7+6
    uint32_t accA[7], accB[7];   // int16x2 packed sums (|S| <= 8128)
    #pragma unroll
    for (int n = 0; n < 7; ++n) { accA[n] = 0u; accB[n] = 0u; }

    // Stage source addressing: 128 rows (cb,k) of 256B per stage; per thread
    // 8 uint4 (row = t>>4, within = t&15).
    uint4 pre[8];
    {
        #pragma unroll
        for (int j = 0; j < 8; ++j) {
            int t = tid + j * 256;
            int row = t >> 4, wi = t & 15;
            pre[j] = *(const uint4*)(g_lut16 + (size_t)row * COUT_ + gz * 128 + wi * 8);
        }
    }

    for (int g = 0; g < 8; ++g) {
        __syncthreads();             // prior stage's gather done
        #pragma unroll
        for (int j = 0; j < 8; ++j) {
            int t = tid + j * 256;
            int row = t >> 4, wi = t & 15;
            *(uint4*)(s_lut16 + row * 128 + wi * 8) = pre[j];
        }
        __syncthreads();
        if (g < 7) {                 // prefetch next stage (hidden behind gather)
            #pragma unroll
            for (int j = 0; j < 8; ++j) {
                int t = tid + j * 256;
                int row = t >> 4, wi = t & 15;
                pre[j] = *(const uint4*)(g_lut16 + (size_t)((g + 1) * 128 + row) * COUT_
                                         + gz * 128 + wi * 8);
            }
        }
        #pragma unroll
        for (int nl = 0; nl < 7; ++nl) {
            int nn = ng * 7 + nl;
            uint2 iw = *(const uint2*)(s_idx + nn * 64 + g * 8);   // 8 idx bytes, broadcast
            #pragma unroll
            for (int c8 = 0; c8 < 8; ++c8) {
                int kk = (int)(((c8 < 4 ? iw.x : iw.y) >> (8 * (c8 & 3))) & 0xFFu);
                const uint2* row = (const uint2*)(s_lut16 + (c8 * KC_ + kk) * 128) + co4;
                uint2 v = *row;                       // 4 couts as s16x2 pairs
                accA[nl] = __vadd2(accA[nl], v.x);
                accB[nl] = __vadd2(accB[nl], v.y);
            }
        }
    }

    float ls = lut_s[0];  int lz = lut_z[0];
    float bs = bias_s[0]; int bz = bias_z[0];
    float os = out_s[0];  float ozf = (float)out_z[0];
    int cobase = gz * 128 + co4 * 4;
    float bd[4];
    #pragma unroll
    for (int j = 0; j < 4; ++j)
        bd[j] = __fmul_rn((float)(bias_q[cobase + j] - bz), bs);

    // Quantize (identical fp math to passing version)
    float fq[7][4];
    #pragma unroll
    for (int nl = 0; nl < 7; ++nl) {
        int S[4];
        S[0] = (int)(short)(accA[nl] & 0xFFFFu);
        S[1] = ((int)accA[nl]) >> 16;
        S[2] = (int)(short)(accB[nl] & 0xFFFFu);
        S[3] = ((int)accB[nl]) >> 16;
        #pragma unroll
        for (int j = 0; j < 4; ++j) {
            float sum = __fmul_rn(ls, (float)(S[j] - 64 * lz));
            float o   = sum + bd[j];
            o = fmaxf(o, 0.f);                                  // relu
            float t = __fadd_rn(__fdiv_rn(o, os), ozf);         // true fp32 div
            t = fminf(t, 127.f);
            t = fmaxf(t, -128.f);
            fq[nl][j] = (float)__float2int_rn(t);               // half-even
        }
    }

    // Transpose via smem (reuse stage buffer): s_f[nn*128 + coL], coL in 0..127
    float4* s4  = (float4*)s_lut16;              // 56*128*4 = 28672 B <= 32 KB
    float*  s_f = (float*)s_lut16;
    __syncthreads();
    #pragma unroll
    for (int nl = 0; nl < 7; ++nl) {
        int nn = ng * 7 + nl;
        s4[nn * 32 + co4] = make_float4(fq[nl][0], fq[nl][1], fq[nl][2], fq[nl][3]);
    }
    __syncthreads();
    if (tid < 128) {   // thread co owns one cout row: 56 floats, stride-128
        int co = tid;
        float v[56];
        #pragma unroll
        for (int p = 0; p < 56; ++p) v[p] = s_f[p * 128 + co];
        float4* dst = (float4*)(out + (size_t)b * COUT_ * NPIX_
                                + (gz * 128 + co) * NPIX_ + tile * 56);
        #pragma unroll
        for (int p = 0; p < 14; ++p)
            dst[p] = make_float4(v[4*p], v[4*p+1], v[4*p+2], v[4*p+3]);
    }
}

// ---------------------------------------------------------------------------
extern "C" void kernel_launch(void* const* d_in, const int* in_sizes, int n_in,
                              void* d_out, int out_size)
{
    bool alpha = (in_sizes[0] == COUT_);   // bias_q first => alphabetical (fallback)

    const int*   x_q    = (const int*)  d_in[alpha ? 11 : 0];
    const float* x_s    = (const float*)d_in[alpha ? 12 : 1];
    const int*   x_z    = (const int*)  d_in[alpha ? 13 : 2];
    const int*   cq     = (const int*)  d_in[3];
    const float* cs     = (const float*)d_in[4];
    const int*   cz     = (const int*)  d_in[5];
    const int*   lut_q  = (const int*)  d_in[6];
    const float* lut_s  = (const float*)d_in[7];
    const int*   lut_z  = (const int*)  d_in[8];
    const int*   bias_q = (const int*)  d_in[alpha ? 0 : 9];
    const float* bias_s = (const float*)d_in[alpha ? 1 : 10];
    const int*   bias_z = (const int*)  d_in[alpha ? 2 : 11];
    const float* out_s  = (const float*)d_in[alpha ? 9 : 12];
    const int*   out_z  = (const int*)  d_in[alpha ? 10 : 13];

    prep_kernel<<<256, 256>>>(lut_q, cq, cs, cz, x_s);   // full LUT coverage
    idx_kernel<<<dim3(NCB_, B_), 256>>>(x_q, x_z, cq, cz);
    out_kernel<<<dim3(14, B_, 2), 256>>>(bias_q, lut_s, lut_z, bias_s, bias_z,
                                         out_s, out_z, (float*)d_out);
}